// round 1
// baseline (speedup 1.0000x reference)
#include <cuda_runtime.h>
#include <cuda_bf16.h>

#define T_TOK 4096
#define DMODEL 768
#define HID 2048
#define NE 8
#define ALPHA 0.05f

// ---------------- scratch (device globals; no allocation allowed) ----------
__device__ int   g_expert[T_TOK];
__device__ float g_gate[T_TOK];
__device__ int   g_counts[NE];
__device__ int   g_off[NE + 1];
__device__ int   g_cursor[NE];
__device__ float g_ce[NE];
__device__ int   g_tok[T_TOK];
__device__ __align__(16) float g_xg[(size_t)T_TOK * DMODEL];      // gathered tokens, expert-contiguous
__device__ __align__(16) float g_h[(size_t)T_TOK * HID];          // silu(u)*v intermediate

// ---------------- init ------------------------------------------------------
__global__ void init_kernel() {
    int i = threadIdx.x;
    if (i < NE) { g_counts[i] = 0; g_ce[i] = 0.f; }
}

// ---------------- gating: logits, softmax, argmax, ce/count accumulation ---
__global__ void gate_kernel(const float* __restrict__ x,
                            const float* __restrict__ wgw,
                            const float* __restrict__ wgb) {
    __shared__ float s_ce[NE];
    __shared__ int   s_cnt[NE];
    int tid = threadIdx.x;
    if (tid < NE) { s_ce[tid] = 0.f; s_cnt[tid] = 0; }
    __syncthreads();

    int warp = tid >> 5, lane = tid & 31;
    int t = blockIdx.x * 8 + warp;   // 512 blocks * 8 warps = 4096 tokens

    float acc[NE];
#pragma unroll
    for (int e = 0; e < NE; e++) acc[e] = 0.f;

    const float* xr = x + (size_t)t * DMODEL;
    for (int i = lane; i < DMODEL; i += 32) {
        float xv = xr[i];
#pragma unroll
        for (int e = 0; e < NE; e++) acc[e] += xv * wgw[e * DMODEL + i];
    }
#pragma unroll
    for (int e = 0; e < NE; e++) {
#pragma unroll
        for (int o = 16; o > 0; o >>= 1) acc[e] += __shfl_xor_sync(0xFFFFFFFFu, acc[e], o);
    }

    if (lane == 0) {
        float mx = -1e30f; int be = 0;
#pragma unroll
        for (int e = 0; e < NE; e++) {
            acc[e] += wgb[e];
            if (acc[e] > mx) { mx = acc[e]; be = e; }   // strict > => first max (jnp.argmax)
        }
        float p[NE]; float s = 0.f;
#pragma unroll
        for (int e = 0; e < NE; e++) { p[e] = __expf(acc[e] - mx); s += p[e]; }
        float inv = 1.f / s;
#pragma unroll
        for (int e = 0; e < NE; e++) { p[e] *= inv; atomicAdd(&s_ce[e], p[e]); }
        g_expert[t] = be;
        g_gate[t]   = p[be];
        atomicAdd(&s_cnt[be], 1);
    }
    __syncthreads();
    if (tid < NE) {
        atomicAdd(&g_ce[tid], s_ce[tid]);
        atomicAdd(&g_counts[tid], s_cnt[tid]);
    }
}

// ---------------- exclusive scan over 8 counts -----------------------------
__global__ void scan_kernel() {
    if (threadIdx.x == 0) {
        int s = 0;
        for (int e = 0; e < NE; e++) {
            g_off[e] = s; g_cursor[e] = s; s += g_counts[e];
        }
        g_off[NE] = s;
    }
}

// ---------------- gather tokens into expert-contiguous layout --------------
__global__ void gather_kernel(const float* __restrict__ x) {
    __shared__ int s_pos;
    int t = blockIdx.x;
    if (threadIdx.x == 0) {
        int e = g_expert[t];
        int pos = atomicAdd(&g_cursor[e], 1);
        g_tok[pos] = t;
        s_pos = pos;
    }
    __syncthreads();
    int pos = s_pos;
    const float4* src = (const float4*)(x + (size_t)t * DMODEL);
    float4*       dst = (float4*)(g_xg + (size_t)pos * DMODEL);
    for (int i = threadIdx.x; i < DMODEL / 4; i += blockDim.x) dst[i] = src[i];
}

// ---------------- up-projection: H = silu(Xe@Wu) * (Xe@Wv) -----------------
// 64x64 tile, BK=16, 256 threads, 4x4 per thread, dual accumulators (u and v).
#define BM 64
#define BN 64
#define BK 16

__global__ __launch_bounds__(256) void expert_up_kernel(const float* __restrict__ Wu,
                                                        const float* __restrict__ Wv) {
    int e    = blockIdx.z;
    int mEnd = g_off[e + 1];
    int m0   = g_off[e] + blockIdx.y * BM;
    if (m0 >= mEnd) return;
    int n0 = blockIdx.x * BN;

    __shared__ float As[BK][BM + 1];                  // +1 pad kills store bank conflicts
    __shared__ __align__(16) float Bu[BK][BN];
    __shared__ __align__(16) float Bv[BK][BN];

    int tid = threadIdx.x;
    int tx = tid & 15, ty = tid >> 4;                 // tx -> n, ty -> m

    float au[4][4], av[4][4];
#pragma unroll
    for (int i = 0; i < 4; i++)
#pragma unroll
        for (int j = 0; j < 4; j++) { au[i][j] = 0.f; av[i][j] = 0.f; }

    const float* WuE = Wu + (size_t)e * DMODEL * HID;
    const float* WvE = Wv + (size_t)e * DMODEL * HID;

    int ar = tid >> 2, akq = tid & 3;                 // A loader: row, k-quad
    int br = tid >> 4, bc = (tid & 15) * 4;           // B loader: k-row, col

    for (int k0 = 0; k0 < DMODEL; k0 += BK) {
        int gm = m0 + ar;
        float4 a4 = (gm < mEnd)
            ? *(const float4*)&g_xg[(size_t)gm * DMODEL + k0 + akq * 4]
            : make_float4(0.f, 0.f, 0.f, 0.f);
        As[akq * 4 + 0][ar] = a4.x; As[akq * 4 + 1][ar] = a4.y;
        As[akq * 4 + 2][ar] = a4.z; As[akq * 4 + 3][ar] = a4.w;

        *(float4*)&Bu[br][bc] = *(const float4*)&WuE[(size_t)(k0 + br) * HID + n0 + bc];
        *(float4*)&Bv[br][bc] = *(const float4*)&WvE[(size_t)(k0 + br) * HID + n0 + bc];
        __syncthreads();

#pragma unroll
        for (int k = 0; k < BK; k++) {
            float ra[4], rbu[4], rbv[4];
#pragma unroll
            for (int i = 0; i < 4; i++) ra[i] = As[k][ty * 4 + i];
#pragma unroll
            for (int j = 0; j < 4; j++) { rbu[j] = Bu[k][tx * 4 + j]; rbv[j] = Bv[k][tx * 4 + j]; }
#pragma unroll
            for (int i = 0; i < 4; i++)
#pragma unroll
                for (int j = 0; j < 4; j++) {
                    au[i][j] += ra[i] * rbu[j];
                    av[i][j] += ra[i] * rbv[j];
                }
        }
        __syncthreads();
    }

#pragma unroll
    for (int i = 0; i < 4; i++) {
        int gm = m0 + ty * 4 + i;
        if (gm >= mEnd) continue;
        float4 hv;
        float* hp = (float*)&hv;
#pragma unroll
        for (int j = 0; j < 4; j++) {
            float u = au[i][j];
            hp[j] = u / (1.f + __expf(-u)) * av[i][j];   // silu(u)*v
        }
        *(float4*)&g_h[(size_t)gm * HID + n0 + tx * 4] = hv;
    }
}

// ---------------- down-projection: y[token] = gate * (H @ Wd[e]) -----------
__global__ __launch_bounds__(256) void expert_down_kernel(const float* __restrict__ Wd,
                                                          float* __restrict__ out) {
    int e    = blockIdx.z;
    int mEnd = g_off[e + 1];
    int m0   = g_off[e] + blockIdx.y * BM;
    if (m0 >= mEnd) return;
    int n0 = blockIdx.x * BN;

    __shared__ float As[BK][BM + 1];
    __shared__ __align__(16) float Bs[BK][BN];

    int tid = threadIdx.x;
    int tx = tid & 15, ty = tid >> 4;

    float acc[4][4];
#pragma unroll
    for (int i = 0; i < 4; i++)
#pragma unroll
        for (int j = 0; j < 4; j++) acc[i][j] = 0.f;

    const float* WdE = Wd + (size_t)e * HID * DMODEL;

    int ar = tid >> 2, akq = tid & 3;
    int br = tid >> 4, bc = (tid & 15) * 4;

    for (int k0 = 0; k0 < HID; k0 += BK) {
        int gm = m0 + ar;
        float4 a4 = (gm < mEnd)
            ? *(const float4*)&g_h[(size_t)gm * HID + k0 + akq * 4]
            : make_float4(0.f, 0.f, 0.f, 0.f);
        As[akq * 4 + 0][ar] = a4.x; As[akq * 4 + 1][ar] = a4.y;
        As[akq * 4 + 2][ar] = a4.z; As[akq * 4 + 3][ar] = a4.w;

        *(float4*)&Bs[br][bc] = *(const float4*)&WdE[(size_t)(k0 + br) * DMODEL + n0 + bc];
        __syncthreads();

#pragma unroll
        for (int k = 0; k < BK; k++) {
            float ra[4], rb[4];
#pragma unroll
            for (int i = 0; i < 4; i++) ra[i] = As[k][ty * 4 + i];
#pragma unroll
            for (int j = 0; j < 4; j++) rb[j] = Bs[k][tx * 4 + j];
#pragma unroll
            for (int i = 0; i < 4; i++)
#pragma unroll
                for (int j = 0; j < 4; j++) acc[i][j] += ra[i] * rb[j];
        }
        __syncthreads();
    }

#pragma unroll
    for (int i = 0; i < 4; i++) {
        int gm = m0 + ty * 4 + i;
        if (gm >= mEnd) continue;
        int   token = g_tok[gm];
        float gate  = g_gate[token];
        float4 yv;
        float* yp = (float*)&yv;
#pragma unroll
        for (int j = 0; j < 4; j++) yp[j] = acc[i][j] * gate;
        *(float4*)&out[(size_t)token * DMODEL + n0 + tx * 4] = yv;
    }
}

// ---------------- aux loss scalar ------------------------------------------
__global__ void aux_kernel(float* __restrict__ out) {
    float s = 0.f;
    for (int e = 0; e < NE; e++) {
        float me = (float)g_counts[e] / (float)T_TOK;
        float ce = g_ce[e] / (float)T_TOK;
        s += me * ce;
    }
    out[(size_t)T_TOK * DMODEL] = ALPHA * NE * s;
}

// ---------------- launch ----------------------------------------------------
extern "C" void kernel_launch(void* const* d_in, const int* in_sizes, int n_in,
                              void* d_out, int out_size) {
    const float* x   = (const float*)d_in[0];
    const float* wgw = (const float*)d_in[1];
    const float* wgb = (const float*)d_in[2];
    const float* Wu  = (const float*)d_in[3];
    const float* Wv  = (const float*)d_in[4];
    const float* Wd  = (const float*)d_in[5];
    float* out = (float*)d_out;

    init_kernel<<<1, 32>>>();
    gate_kernel<<<T_TOK / 8, 256>>>(x, wgw, wgb);
    scan_kernel<<<1, 1>>>();
    gather_kernel<<<T_TOK, 192>>>(x);
    expert_up_kernel<<<dim3(HID / BN, T_TOK / BM, NE), 256>>>(Wu, Wv);
    expert_down_kernel<<<dim3(DMODEL / BN, T_TOK / BM, NE), 256>>>(Wd, out);
    aux_kernel<<<1, 1>>>(out);
}

// round 2
// speedup vs baseline: 2.7896x; 2.7896x over previous
#include <cuda_runtime.h>
#include <cuda_bf16.h>
#include <cstdint>

#define T_TOK 4096
#define DMODEL 768
#define HID 2048
#define NE 8
#define ALPHA 0.05f

#define BM 128
#define BN 64
#define BK 32

// ---------------- scratch (device globals; no allocation allowed) ----------
__device__ int   g_expert[T_TOK];
__device__ float g_gate[T_TOK];
__device__ int   g_counts[NE];
__device__ int   g_off[NE + 1];
__device__ int   g_cursor[NE];
__device__ float g_ce[NE];
__device__ int   g_tok[T_TOK];
__device__ __align__(16) float g_xg[(size_t)T_TOK * DMODEL];   // gathered tokens
__device__ __align__(16) float g_h[(size_t)T_TOK * HID];       // silu(u)*v

// ---------------- helpers ---------------------------------------------------
__device__ __forceinline__ uint32_t f2tf(float f) {
    uint32_t u;
    asm("cvt.rna.tf32.f32 %0, %1;" : "=r"(u) : "f"(f));
    return u;
}

#define MMA_TF32(d, a, b0, b1)                                                  \
    asm volatile("mma.sync.aligned.m16n8k8.row.col.f32.tf32.tf32.f32 "          \
                 "{%0,%1,%2,%3}, {%4,%5,%6,%7}, {%8,%9}, {%0,%1,%2,%3};"        \
                 : "+f"(d[0]), "+f"(d[1]), "+f"(d[2]), "+f"(d[3])               \
                 : "r"(a[0]), "r"(a[1]), "r"(a[2]), "r"(a[3]), "r"(b0), "r"(b1))

// ---------------- init ------------------------------------------------------
__global__ void init_kernel() {
    int i = threadIdx.x;
    if (i < NE) { g_counts[i] = 0; g_ce[i] = 0.f; }
}

// ---------------- gating ----------------------------------------------------
__global__ void gate_kernel(const float* __restrict__ x,
                            const float* __restrict__ wgw,
                            const float* __restrict__ wgb) {
    __shared__ float s_ce[NE];
    __shared__ int   s_cnt[NE];
    int tid = threadIdx.x;
    if (tid < NE) { s_ce[tid] = 0.f; s_cnt[tid] = 0; }
    __syncthreads();

    int warp = tid >> 5, lane = tid & 31;
    int t = blockIdx.x * 8 + warp;

    float acc[NE];
#pragma unroll
    for (int e = 0; e < NE; e++) acc[e] = 0.f;

    const float* xr = x + (size_t)t * DMODEL;
    for (int i = lane; i < DMODEL; i += 32) {
        float xv = xr[i];
#pragma unroll
        for (int e = 0; e < NE; e++) acc[e] += xv * wgw[e * DMODEL + i];
    }
#pragma unroll
    for (int e = 0; e < NE; e++) {
#pragma unroll
        for (int o = 16; o > 0; o >>= 1) acc[e] += __shfl_xor_sync(0xFFFFFFFFu, acc[e], o);
    }

    if (lane == 0) {
        float mx = -1e30f; int be = 0;
#pragma unroll
        for (int e = 0; e < NE; e++) {
            acc[e] += wgb[e];
            if (acc[e] > mx) { mx = acc[e]; be = e; }
        }
        float p[NE]; float s = 0.f;
#pragma unroll
        for (int e = 0; e < NE; e++) { p[e] = __expf(acc[e] - mx); s += p[e]; }
        float inv = 1.f / s;
#pragma unroll
        for (int e = 0; e < NE; e++) { p[e] *= inv; atomicAdd(&s_ce[e], p[e]); }
        g_expert[t] = be;
        g_gate[t]   = p[be];
        atomicAdd(&s_cnt[be], 1);
    }
    __syncthreads();
    if (tid < NE) {
        atomicAdd(&g_ce[tid], s_ce[tid]);
        atomicAdd(&g_counts[tid], s_cnt[tid]);
    }
}

// ---------------- scan ------------------------------------------------------
__global__ void scan_kernel() {
    if (threadIdx.x == 0) {
        int s = 0;
        for (int e = 0; e < NE; e++) { g_off[e] = s; g_cursor[e] = s; s += g_counts[e]; }
        g_off[NE] = s;
    }
}

// ---------------- gather ----------------------------------------------------
__global__ void gather_kernel(const float* __restrict__ x) {
    __shared__ int s_pos;
    int t = blockIdx.x;
    if (threadIdx.x == 0) {
        int e = g_expert[t];
        int pos = atomicAdd(&g_cursor[e], 1);
        g_tok[pos] = t;
        s_pos = pos;
    }
    __syncthreads();
    int pos = s_pos;
    const float4* src = (const float4*)(x + (size_t)t * DMODEL);
    float4*       dst = (float4*)(g_xg + (size_t)pos * DMODEL);
    for (int i = threadIdx.x; i < DMODEL / 4; i += blockDim.x) dst[i] = src[i];
}

// ---------------- up-projection: H = silu(Xe@Wu) * (Xe@Wv), tf32 MMA -------
// 128x64 tile, BK=32, 256 thr (8 warps: 4m x 2n), warp tile 32x32.
__global__ __launch_bounds__(256, 2) void expert_up_kernel(const float* __restrict__ Wu,
                                                           const float* __restrict__ Wv) {
    int e    = blockIdx.z;
    int mEnd = g_off[e + 1];
    int m0   = g_off[e] + blockIdx.y * BM;
    if (m0 >= mEnd) return;
    int n0 = blockIdx.x * BN;

    __shared__ uint32_t As[BM][36];       // stride 36: frag banks (4g+t), 16B-aligned rows
    __shared__ uint32_t Bus[BK][72];      // stride 72: frag banks (8k+n), 16B-aligned rows
    __shared__ uint32_t Bvs[BK][72];

    int tid  = threadIdx.x;
    int wid  = tid >> 5, lane = tid & 31;
    int wm   = wid & 3, wn = wid >> 2;    // 4 x 2 warp grid
    int gid  = lane >> 2, tig = lane & 3;

    float au[2][4][4], av[2][4][4];
#pragma unroll
    for (int mt = 0; mt < 2; mt++)
#pragma unroll
        for (int nt = 0; nt < 4; nt++)
#pragma unroll
            for (int r = 0; r < 4; r++) { au[mt][nt][r] = 0.f; av[mt][nt][r] = 0.f; }

    const float* WuE = Wu + (size_t)e * DMODEL * HID;
    const float* WvE = Wv + (size_t)e * DMODEL * HID;

    for (int k0 = 0; k0 < DMODEL; k0 += BK) {
        // A tile: 128 x 32, 1024 float4 loads
#pragma unroll
        for (int q = 0; q < 4; q++) {
            int idx = tid + q * 256;
            int r = idx >> 3, c = (idx & 7) * 4;
            int gm = m0 + r;
            float4 a4 = (gm < mEnd) ? *(const float4*)&g_xg[(size_t)gm * DMODEL + k0 + c]
                                    : make_float4(0.f, 0.f, 0.f, 0.f);
            uint4 t4 = make_uint4(f2tf(a4.x), f2tf(a4.y), f2tf(a4.z), f2tf(a4.w));
            *(uint4*)&As[r][c] = t4;
        }
        // B tiles: 32 x 64 each
#pragma unroll
        for (int q = 0; q < 2; q++) {
            int idx = tid + q * 256;
            int r = idx >> 4, c = (idx & 15) * 4;
            size_t goff = (size_t)(k0 + r) * HID + n0 + c;
            float4 u4 = *(const float4*)&WuE[goff];
            float4 v4 = *(const float4*)&WvE[goff];
            *(uint4*)&Bus[r][c] = make_uint4(f2tf(u4.x), f2tf(u4.y), f2tf(u4.z), f2tf(u4.w));
            *(uint4*)&Bvs[r][c] = make_uint4(f2tf(v4.x), f2tf(v4.y), f2tf(v4.z), f2tf(v4.w));
        }
        __syncthreads();

#pragma unroll
        for (int kc = 0; kc < 4; kc++) {
            uint32_t a[2][4];
#pragma unroll
            for (int mt = 0; mt < 2; mt++) {
                int r = wm * 32 + mt * 16 + gid;
                int c = kc * 8 + tig;
                a[mt][0] = As[r][c];
                a[mt][1] = As[r + 8][c];
                a[mt][2] = As[r][c + 4];
                a[mt][3] = As[r + 8][c + 4];
            }
#pragma unroll
            for (int nt = 0; nt < 4; nt++) {
                int cn = wn * 32 + nt * 8 + gid;
                int rk = kc * 8 + tig;
                uint32_t bu0 = Bus[rk][cn], bu1 = Bus[rk + 4][cn];
                uint32_t bv0 = Bvs[rk][cn], bv1 = Bvs[rk + 4][cn];
#pragma unroll
                for (int mt = 0; mt < 2; mt++) {
                    MMA_TF32(au[mt][nt], a[mt], bu0, bu1);
                    MMA_TF32(av[mt][nt], a[mt], bv0, bv1);
                }
            }
        }
        __syncthreads();
    }

    // epilogue: silu(u)*v
#pragma unroll
    for (int mt = 0; mt < 2; mt++) {
#pragma unroll
        for (int nt = 0; nt < 4; nt++) {
            int r0 = m0 + wm * 32 + mt * 16 + gid;
            int cc = n0 + wn * 32 + nt * 8 + tig * 2;
            if (r0 < mEnd) {
                float u0 = au[mt][nt][0], u1 = au[mt][nt][1];
                float2 h0 = make_float2(u0 / (1.f + __expf(-u0)) * av[mt][nt][0],
                                        u1 / (1.f + __expf(-u1)) * av[mt][nt][1]);
                *(float2*)&g_h[(size_t)r0 * HID + cc] = h0;
            }
            int r1 = r0 + 8;
            if (r1 < mEnd) {
                float u2 = au[mt][nt][2], u3 = au[mt][nt][3];
                float2 h1 = make_float2(u2 / (1.f + __expf(-u2)) * av[mt][nt][2],
                                        u3 / (1.f + __expf(-u3)) * av[mt][nt][3]);
                *(float2*)&g_h[(size_t)r1 * HID + cc] = h1;
            }
        }
    }
}

// ---------------- down-projection: y[token] = gate * (H @ Wd[e]), tf32 MMA --
__global__ __launch_bounds__(256, 2) void expert_down_kernel(const float* __restrict__ Wd,
                                                             float* __restrict__ out) {
    int e    = blockIdx.z;
    int mEnd = g_off[e + 1];
    int m0   = g_off[e] + blockIdx.y * BM;
    if (m0 >= mEnd) return;
    int n0 = blockIdx.x * BN;

    __shared__ uint32_t As[BM][36];
    __shared__ uint32_t Bs[BK][72];

    int tid  = threadIdx.x;
    int wid  = tid >> 5, lane = tid & 31;
    int wm   = wid & 3, wn = wid >> 2;
    int gid  = lane >> 2, tig = lane & 3;

    float acc[2][4][4];
#pragma unroll
    for (int mt = 0; mt < 2; mt++)
#pragma unroll
        for (int nt = 0; nt < 4; nt++)
#pragma unroll
            for (int r = 0; r < 4; r++) acc[mt][nt][r] = 0.f;

    const float* WdE = Wd + (size_t)e * HID * DMODEL;

    for (int k0 = 0; k0 < HID; k0 += BK) {
#pragma unroll
        for (int q = 0; q < 4; q++) {
            int idx = tid + q * 256;
            int r = idx >> 3, c = (idx & 7) * 4;
            int gm = m0 + r;
            float4 a4 = (gm < mEnd) ? *(const float4*)&g_h[(size_t)gm * HID + k0 + c]
                                    : make_float4(0.f, 0.f, 0.f, 0.f);
            *(uint4*)&As[r][c] = make_uint4(f2tf(a4.x), f2tf(a4.y), f2tf(a4.z), f2tf(a4.w));
        }
#pragma unroll
        for (int q = 0; q < 2; q++) {
            int idx = tid + q * 256;
            int r = idx >> 4, c = (idx & 15) * 4;
            float4 b4 = *(const float4*)&WdE[(size_t)(k0 + r) * DMODEL + n0 + c];
            *(uint4*)&Bs[r][c] = make_uint4(f2tf(b4.x), f2tf(b4.y), f2tf(b4.z), f2tf(b4.w));
        }
        __syncthreads();

#pragma unroll
        for (int kc = 0; kc < 4; kc++) {
            uint32_t a[2][4];
#pragma unroll
            for (int mt = 0; mt < 2; mt++) {
                int r = wm * 32 + mt * 16 + gid;
                int c = kc * 8 + tig;
                a[mt][0] = As[r][c];
                a[mt][1] = As[r + 8][c];
                a[mt][2] = As[r][c + 4];
                a[mt][3] = As[r + 8][c + 4];
            }
#pragma unroll
            for (int nt = 0; nt < 4; nt++) {
                int cn = wn * 32 + nt * 8 + gid;
                int rk = kc * 8 + tig;
                uint32_t b0 = Bs[rk][cn], b1 = Bs[rk + 4][cn];
#pragma unroll
                for (int mt = 0; mt < 2; mt++) {
                    MMA_TF32(acc[mt][nt], a[mt], b0, b1);
                }
            }
        }
        __syncthreads();
    }

#pragma unroll
    for (int mt = 0; mt < 2; mt++) {
#pragma unroll
        for (int nt = 0; nt < 4; nt++) {
            int r0 = m0 + wm * 32 + mt * 16 + gid;
            int cc = n0 + wn * 32 + nt * 8 + tig * 2;
            if (r0 < mEnd) {
                int   token = g_tok[r0];
                float gate  = g_gate[token];
                *(float2*)&out[(size_t)token * DMODEL + cc] =
                    make_float2(acc[mt][nt][0] * gate, acc[mt][nt][1] * gate);
            }
            int r1 = r0 + 8;
            if (r1 < mEnd) {
                int   token = g_tok[r1];
                float gate  = g_gate[token];
                *(float2*)&out[(size_t)token * DMODEL + cc] =
                    make_float2(acc[mt][nt][2] * gate, acc[mt][nt][3] * gate);
            }
        }
    }
}

// ---------------- aux -------------------------------------------------------
__global__ void aux_kernel(float* __restrict__ out) {
    float s = 0.f;
    for (int e = 0; e < NE; e++) {
        float me = (float)g_counts[e] / (float)T_TOK;
        float ce = g_ce[e] / (float)T_TOK;
        s += me * ce;
    }
    out[(size_t)T_TOK * DMODEL] = ALPHA * NE * s;
}

// ---------------- launch ----------------------------------------------------
extern "C" void kernel_launch(void* const* d_in, const int* in_sizes, int n_in,
                              void* d_out, int out_size) {
    const float* x   = (const float*)d_in[0];
    const float* wgw = (const float*)d_in[1];
    const float* wgb = (const float*)d_in[2];
    const float* Wu  = (const float*)d_in[3];
    const float* Wv  = (const float*)d_in[4];
    const float* Wd  = (const float*)d_in[5];
    float* out = (float*)d_out;

    init_kernel<<<1, 32>>>();
    gate_kernel<<<T_TOK / 8, 256>>>(x, wgw, wgb);
    scan_kernel<<<1, 1>>>();
    gather_kernel<<<T_TOK, 192>>>(x);
    expert_up_kernel<<<dim3(HID / BN, T_TOK / BM, NE), 256>>>(Wu, Wv);
    expert_down_kernel<<<dim3(DMODEL / BN, T_TOK / BM, NE), 256>>>(Wd, out);
    aux_kernel<<<1, 1>>>(out);
}

// round 4
// speedup vs baseline: 4.8206x; 1.7280x over previous
#include <cuda_runtime.h>
#include <cuda_fp16.h>
#include <cstdint>

#define T_TOK 4096
#define DMODEL 768
#define HID 2048
#define NE 8
#define ALPHA 0.05f

#define AST 40          // A smem row stride in halves (80B, conflict-free for ldmatrix)
#define BST 72          // B smem row stride in halves (144B, conflict-free for ldmatrix.trans)
#define NC_UP (DMODEL / 32)   // 24 k-chunks
#define NC_DN (HID / 32)      // 64 k-chunks

// ---------------- scratch ----------------------------------------------------
__device__ int   g_expert[T_TOK];
__device__ float g_gate[T_TOK];
__device__ int   g_counts[NE];
__device__ int   g_off[NE + 1];
__device__ int   g_cursor[NE];
__device__ float g_ce[NE];
__device__ int   g_tok[T_TOK];
__device__ __align__(16) __half g_xg[(size_t)T_TOK * DMODEL];  // fp16 tokens, expert-sorted
__device__ __align__(16) __half g_h[(size_t)T_TOK * HID];      // fp16 silu(u)*v

// ---------------- helpers ----------------------------------------------------
__device__ __forceinline__ uint32_t smem_u32(const void* p) {
    uint32_t a;
    asm("{ .reg .u64 t; cvta.to.shared.u64 t, %1; cvt.u32.u64 %0, t; }" : "=r"(a) : "l"(p));
    return a;
}
__device__ __forceinline__ uint32_t pk(float a, float b) {
    __half2 h = __floats2half2_rn(a, b);
    return *reinterpret_cast<uint32_t*>(&h);
}
__device__ __forceinline__ void cpa16(uint32_t dst, const void* src, bool valid) {
    int sz = valid ? 16 : 0;
    asm volatile("cp.async.cg.shared.global [%0], [%1], 16, %2;\n"
                 :: "r"(dst), "l"(src), "r"(sz) : "memory");
}
#define CP_COMMIT() asm volatile("cp.async.commit_group;" ::: "memory")
#define CP_WAIT0()  asm volatile("cp.async.wait_group 0;" ::: "memory")

#define LDSM_X4(r0, r1, r2, r3, a)                                              \
    asm volatile("ldmatrix.sync.aligned.m8n8.x4.shared.b16 {%0,%1,%2,%3}, [%4];"\
                 : "=r"(r0), "=r"(r1), "=r"(r2), "=r"(r3) : "r"(a))
#define LDSM_X4T(r0, r1, r2, r3, a)                                             \
    asm volatile("ldmatrix.sync.aligned.m8n8.x4.trans.shared.b16 {%0,%1,%2,%3}, [%4];"\
                 : "=r"(r0), "=r"(r1), "=r"(r2), "=r"(r3) : "r"(a))

#define MMA16816(d, a, b0, b1)                                                  \
    asm volatile("mma.sync.aligned.m16n8k16.row.col.f32.f16.f16.f32 "           \
                 "{%0,%1,%2,%3},{%4,%5,%6,%7},{%8,%9},{%0,%1,%2,%3};"           \
                 : "+f"((d)[0]), "+f"((d)[1]), "+f"((d)[2]), "+f"((d)[3])       \
                 : "r"((a)[0]), "r"((a)[1]), "r"((a)[2]), "r"((a)[3]),          \
                   "r"(b0), "r"(b1))

// ---------------- small kernels ----------------------------------------------
__global__ void init_kernel() {
    int i = threadIdx.x;
    if (i < NE) { g_counts[i] = 0; g_ce[i] = 0.f; }
}

__global__ void gate_kernel(const float* __restrict__ x,
                            const float* __restrict__ wgw,
                            const float* __restrict__ wgb) {
    __shared__ float s_ce[NE];
    __shared__ int   s_cnt[NE];
    int tid = threadIdx.x;
    if (tid < NE) { s_ce[tid] = 0.f; s_cnt[tid] = 0; }
    __syncthreads();

    int warp = tid >> 5, lane = tid & 31;
    int t = blockIdx.x * 8 + warp;

    float acc[NE];
#pragma unroll
    for (int e = 0; e < NE; e++) acc[e] = 0.f;
    const float* xr = x + (size_t)t * DMODEL;
    for (int i = lane; i < DMODEL; i += 32) {
        float xv = xr[i];
#pragma unroll
        for (int e = 0; e < NE; e++) acc[e] += xv * wgw[e * DMODEL + i];
    }
#pragma unroll
    for (int e = 0; e < NE; e++)
#pragma unroll
        for (int o = 16; o > 0; o >>= 1) acc[e] += __shfl_xor_sync(0xFFFFFFFFu, acc[e], o);

    if (lane == 0) {
        float mx = -1e30f; int be = 0;
#pragma unroll
        for (int e = 0; e < NE; e++) {
            acc[e] += wgb[e];
            if (acc[e] > mx) { mx = acc[e]; be = e; }
        }
        float p[NE]; float s = 0.f;
#pragma unroll
        for (int e = 0; e < NE; e++) { p[e] = __expf(acc[e] - mx); s += p[e]; }
        float inv = 1.f / s;
#pragma unroll
        for (int e = 0; e < NE; e++) { p[e] *= inv; atomicAdd(&s_ce[e], p[e]); }
        g_expert[t] = be;
        g_gate[t]   = p[be];
        atomicAdd(&s_cnt[be], 1);
    }
    __syncthreads();
    if (tid < NE) { atomicAdd(&g_ce[tid], s_ce[tid]); atomicAdd(&g_counts[tid], s_cnt[tid]); }
}

__global__ void scan_kernel() {
    if (threadIdx.x == 0) {
        int s = 0;
        for (int e = 0; e < NE; e++) { g_off[e] = s; g_cursor[e] = s; s += g_counts[e]; }
        g_off[NE] = s;
    }
}

__global__ void gather_kernel(const float* __restrict__ x) {
    __shared__ int s_pos;
    int t = blockIdx.x;
    if (threadIdx.x == 0) {
        int e = g_expert[t];
        int pos = atomicAdd(&g_cursor[e], 1);
        g_tok[pos] = t;
        s_pos = pos;
    }
    __syncthreads();
    int pos = s_pos;
    const float4* src = (const float4*)(x + (size_t)t * DMODEL);
    __half2* dst = (__half2*)(g_xg + (size_t)pos * DMODEL);
    for (int i = threadIdx.x; i < DMODEL / 4; i += blockDim.x) {
        float4 v = src[i];
        dst[i * 2 + 0] = __floats2half2_rn(v.x, v.y);
        dst[i * 2 + 1] = __floats2half2_rn(v.z, v.w);
    }
}

// ---------------- up: H = silu(Xe@Wu)*(Xe@Wv), fp16 mma + ldmatrix ----------
// BM=128, BN=64, BK=32. 8 warps (4m x 2n), warp tile 32x32.
__global__ __launch_bounds__(256) void up_mma(const float* __restrict__ Wu,
                                              const float* __restrict__ Wv) {
    int e    = blockIdx.z;
    int mEnd = g_off[e + 1];
    int m0   = g_off[e] + blockIdx.y * 128;
    if (m0 >= mEnd) return;
    int n0 = blockIdx.x * 64;

    __shared__ __align__(16) __half As[2][128 * AST];
    __shared__ __align__(16) __half Bu[2][32 * BST];
    __shared__ __align__(16) __half Bv[2][32 * BST];

    int tid = threadIdx.x, lane = tid & 31, wid = tid >> 5;
    int wm = wid & 3, wn = wid >> 2;
    int lg = lane >> 2, lt = lane & 3;

    uint32_t aA[2] = { smem_u32(As[0]), smem_u32(As[1]) };
    uint32_t aU[2] = { smem_u32(Bu[0]), smem_u32(Bu[1]) };
    uint32_t aV[2] = { smem_u32(Bv[0]), smem_u32(Bv[1]) };

    const float* WuE = Wu + (size_t)e * DMODEL * HID;
    const float* WvE = Wv + (size_t)e * DMODEL * HID;

    float au[2][4][4], av[2][4][4];
#pragma unroll
    for (int mt = 0; mt < 2; mt++)
#pragma unroll
        for (int nt = 0; nt < 4; nt++)
#pragma unroll
            for (int r = 0; r < 4; r++) { au[mt][nt][r] = 0.f; av[mt][nt][r] = 0.f; }

    int brow = tid >> 3, bcol = (tid & 7) * 8;     // B loader: k-row, 8 n-cols
    float pu[8], pv[8];

    // A loader: 512 16B-segments, 2 per thread
    auto issueA = [&](int c, int st) {
#pragma unroll
        for (int q = 0; q < 2; q++) {
            int sidx = tid + q * 256;
            int row = sidx >> 2, sg = sidx & 3;
            int gm = m0 + row;
            bool v = gm < mEnd;
            uint32_t dst = aA[st] + (uint32_t)(row * AST + sg * 8) * 2;
            const __half* src = &g_xg[(size_t)(v ? gm : m0) * DMODEL + c * 32 + sg * 8];
            cpa16(dst, src, v);
        }
    };
    auto ldgB = [&](int c) {
        const float* ru = &WuE[(size_t)(c * 32 + brow) * HID + n0 + bcol];
        const float* rv = &WvE[(size_t)(c * 32 + brow) * HID + n0 + bcol];
        *(float4*)&pu[0] = *(const float4*)ru;  *(float4*)&pu[4] = *(const float4*)(ru + 4);
        *(float4*)&pv[0] = *(const float4*)rv;  *(float4*)&pv[4] = *(const float4*)(rv + 4);
    };
    auto stsB = [&](int st) {
        *(uint4*)&Bu[st][brow * BST + bcol] =
            make_uint4(pk(pu[0], pu[1]), pk(pu[2], pu[3]), pk(pu[4], pu[5]), pk(pu[6], pu[7]));
        *(uint4*)&Bv[st][brow * BST + bcol] =
            make_uint4(pk(pv[0], pv[1]), pk(pv[2], pv[3]), pk(pv[4], pv[5]), pk(pv[6], pv[7]));
    };
    auto compute = [&](int st) {
#pragma unroll
        for (int s = 0; s < 2; s++) {
            int k0 = s * 16;
            uint32_t a[2][4];
#pragma unroll
            for (int mt = 0; mt < 2; mt++) {
                uint32_t ad = aA[st] + (uint32_t)(((wm * 32 + mt * 16 + (lane & 15)) * AST)
                                                  + k0 + (lane >> 4) * 8) * 2;
                LDSM_X4(a[mt][0], a[mt][1], a[mt][2], a[mt][3], ad);
            }
#pragma unroll
            for (int np = 0; np < 2; np++) {
                uint32_t boff = (uint32_t)(((k0 + (lane & 15)) * BST)
                                           + wn * 32 + np * 16 + (lane >> 4) * 8) * 2;
                uint32_t u0, u1, u2, u3, v0, v1, v2, v3;
                LDSM_X4T(u0, u1, u2, u3, aU[st] + boff);
                LDSM_X4T(v0, v1, v2, v3, aV[st] + boff);
#pragma unroll
                for (int mt = 0; mt < 2; mt++) {
                    MMA16816(au[mt][np * 2 + 0], a[mt], u0, u1);
                    MMA16816(au[mt][np * 2 + 1], a[mt], u2, u3);
                    MMA16816(av[mt][np * 2 + 0], a[mt], v0, v1);
                    MMA16816(av[mt][np * 2 + 1], a[mt], v2, v3);
                }
            }
        }
    };

    issueA(0, 0); ldgB(0); stsB(0);
    CP_COMMIT(); CP_WAIT0(); __syncthreads();

    for (int c = 0; c < NC_UP; c++) {
        int buf = c & 1;
        bool pf = (c + 1) < NC_UP;
        if (pf) { issueA(c + 1, buf ^ 1); ldgB(c + 1); }
        compute(buf);
        if (pf) stsB(buf ^ 1);
        CP_COMMIT(); CP_WAIT0(); __syncthreads();
    }

    // epilogue: silu(u)*v -> g_h (fp16)
#pragma unroll
    for (int mt = 0; mt < 2; mt++) {
#pragma unroll
        for (int nt = 0; nt < 4; nt++) {
            int row0 = m0 + wm * 32 + mt * 16 + lg;
            int col  = n0 + wn * 32 + nt * 8 + lt * 2;
            if (row0 < mEnd) {
                float u0 = au[mt][nt][0], u1 = au[mt][nt][1];
                float h0 = u0 / (1.f + __expf(-u0)) * av[mt][nt][0];
                float h1 = u1 / (1.f + __expf(-u1)) * av[mt][nt][1];
                *(__half2*)&g_h[(size_t)row0 * HID + col] = __floats2half2_rn(h0, h1);
            }
            int row1 = row0 + 8;
            if (row1 < mEnd) {
                float u2 = au[mt][nt][2], u3 = au[mt][nt][3];
                float h2 = u2 / (1.f + __expf(-u2)) * av[mt][nt][2];
                float h3 = u3 / (1.f + __expf(-u3)) * av[mt][nt][3];
                *(__half2*)&g_h[(size_t)row1 * HID + col] = __floats2half2_rn(h2, h3);
            }
        }
    }
}

// ---------------- down: y[token] = gate * (H @ Wd[e]) ------------------------
__global__ __launch_bounds__(256) void dn_mma(const float* __restrict__ Wd,
                                              float* __restrict__ out) {
    int e    = blockIdx.z;
    int mEnd = g_off[e + 1];
    int m0   = g_off[e] + blockIdx.y * 128;
    if (m0 >= mEnd) return;
    int n0 = blockIdx.x * 64;

    __shared__ __align__(16) __half As[2][128 * AST];
    __shared__ __align__(16) __half Bs[2][32 * BST];

    int tid = threadIdx.x, lane = tid & 31, wid = tid >> 5;
    int wm = wid & 3, wn = wid >> 2;
    int lg = lane >> 2, lt = lane & 3;

    uint32_t aA[2] = { smem_u32(As[0]), smem_u32(As[1]) };
    uint32_t aB[2] = { smem_u32(Bs[0]), smem_u32(Bs[1]) };

    const float* WdE = Wd + (size_t)e * HID * DMODEL;

    float acc[2][4][4];
#pragma unroll
    for (int mt = 0; mt < 2; mt++)
#pragma unroll
        for (int nt = 0; nt < 4; nt++)
#pragma unroll
            for (int r = 0; r < 4; r++) acc[mt][nt][r] = 0.f;

    int brow = tid >> 3, bcol = (tid & 7) * 8;
    float pb[8];

    auto issueA = [&](int c, int st) {
#pragma unroll
        for (int q = 0; q < 2; q++) {
            int sidx = tid + q * 256;
            int row = sidx >> 2, sg = sidx & 3;
            int gm = m0 + row;
            bool v = gm < mEnd;
            uint32_t dst = aA[st] + (uint32_t)(row * AST + sg * 8) * 2;
            const __half* src = &g_h[(size_t)(v ? gm : m0) * HID + c * 32 + sg * 8];
            cpa16(dst, src, v);
        }
    };
    auto ldgB = [&](int c) {
        const float* rb = &WdE[(size_t)(c * 32 + brow) * DMODEL + n0 + bcol];
        *(float4*)&pb[0] = *(const float4*)rb;  *(float4*)&pb[4] = *(const float4*)(rb + 4);
    };
    auto stsB = [&](int st) {
        *(uint4*)&Bs[st][brow * BST + bcol] =
            make_uint4(pk(pb[0], pb[1]), pk(pb[2], pb[3]), pk(pb[4], pb[5]), pk(pb[6], pb[7]));
    };
    auto compute = [&](int st) {
#pragma unroll
        for (int s = 0; s < 2; s++) {
            int k0 = s * 16;
            uint32_t a[2][4];
#pragma unroll
            for (int mt = 0; mt < 2; mt++) {
                uint32_t ad = aA[st] + (uint32_t)(((wm * 32 + mt * 16 + (lane & 15)) * AST)
                                                  + k0 + (lane >> 4) * 8) * 2;
                LDSM_X4(a[mt][0], a[mt][1], a[mt][2], a[mt][3], ad);
            }
#pragma unroll
            for (int np = 0; np < 2; np++) {
                uint32_t boff = (uint32_t)(((k0 + (lane & 15)) * BST)
                                           + wn * 32 + np * 16 + (lane >> 4) * 8) * 2;
                uint32_t b0, b1, b2, b3;
                LDSM_X4T(b0, b1, b2, b3, aB[st] + boff);
#pragma unroll
                for (int mt = 0; mt < 2; mt++) {
                    MMA16816(acc[mt][np * 2 + 0], a[mt], b0, b1);
                    MMA16816(acc[mt][np * 2 + 1], a[mt], b2, b3);
                }
            }
        }
    };

    issueA(0, 0); ldgB(0); stsB(0);
    CP_COMMIT(); CP_WAIT0(); __syncthreads();

    for (int c = 0; c < NC_DN; c++) {
        int buf = c & 1;
        bool pf = (c + 1) < NC_DN;
        if (pf) { issueA(c + 1, buf ^ 1); ldgB(c + 1); }
        compute(buf);
        if (pf) stsB(buf ^ 1);
        CP_COMMIT(); CP_WAIT0(); __syncthreads();
    }

#pragma unroll
    for (int mt = 0; mt < 2; mt++) {
#pragma unroll
        for (int nt = 0; nt < 4; nt++) {
            int row0 = m0 + wm * 32 + mt * 16 + lg;
            int col  = n0 + wn * 32 + nt * 8 + lt * 2;
            if (row0 < mEnd) {
                int token = g_tok[row0];
                float gate = g_gate[token];
                *(float2*)&out[(size_t)token * DMODEL + col] =
                    make_float2(acc[mt][nt][0] * gate, acc[mt][nt][1] * gate);
            }
            int row1 = row0 + 8;
            if (row1 < mEnd) {
                int token = g_tok[row1];
                float gate = g_gate[token];
                *(float2*)&out[(size_t)token * DMODEL + col] =
                    make_float2(acc[mt][nt][2] * gate, acc[mt][nt][3] * gate);
            }
        }
    }
}

// ---------------- aux --------------------------------------------------------
__global__ void aux_kernel(float* __restrict__ out) {
    float s = 0.f;
    for (int e = 0; e < NE; e++) {
        float me = (float)g_counts[e] / (float)T_TOK;
        float ce = g_ce[e] / (float)T_TOK;
        s += me * ce;
    }
    out[(size_t)T_TOK * DMODEL] = ALPHA * NE * s;
}

// ---------------- launch -----------------------------------------------------
extern "C" void kernel_launch(void* const* d_in, const int* in_sizes, int n_in,
                              void* d_out, int out_size) {
    const float* x   = (const float*)d_in[0];
    const float* wgw = (const float*)d_in[1];
    const float* wgb = (const float*)d_in[2];
    const float* Wu  = (const float*)d_in[3];
    const float* Wv  = (const float*)d_in[4];
    const float* Wd  = (const float*)d_in[5];
    float* out = (float*)d_out;

    init_kernel<<<1, 32>>>();
    gate_kernel<<<T_TOK / 8, 256>>>(x, wgw, wgb);
    scan_kernel<<<1, 1>>>();
    gather_kernel<<<T_TOK, 192>>>(x);
    up_mma<<<dim3(HID / 64, T_TOK / 128, NE), 256>>>(Wu, Wv);
    dn_mma<<<dim3(DMODEL / 64, T_TOK / 128, NE), 256>>>(Wd, out);
    aux_kernel<<<1, 1>>>(out);
}